// round 1
// baseline (speedup 1.0000x reference)
#include <cuda_runtime.h>
#include <math.h>
#include <math_constants.h>

// Problem constants
#define HEAD_DIM 128
#define NQH      32
#define NKVH     8
#define HIDDEN   4096
#define SEQ      2048
#define KV_COLS  1024          // NKVH * HEAD_DIM
#define NCHUNK   32
#define CHUNK_ROWS 128         // 4096 / NCHUNK
#define TOT_COLS 6144          // HIDDEN + 2*KV_COLS

// ---------------- scratch (no allocations allowed) ----------------
__device__ float d_partial[NCHUNK * TOT_COLS];   // colsum partials
__device__ float d_cq[HIDDEN];                   // colsum(Wq)
__device__ float d_ck[KV_COLS];                  // colsum(Wk)
__device__ float d_cv[KV_COLS];                  // colsum(Wv)
__device__ float d_g[NQH * SEQ];                 // per-head relative-position score table
__device__ float d_M[NQH * HIDDEN];              // M[h,j] = sum_d cv[kvh,d]*Wo[h*128+d, j]
__device__ float d_w[NQH * SEQ];                 // w[h,q] = sum_k attn(h,q,k)*ids[k]

// ---------------- stage 1: partial column sums of Wq, Wk, Wv ----------------
__global__ void __launch_bounds__(256) colsum_stage1(const float* __restrict__ Wq,
                                                     const float* __restrict__ Wk,
                                                     const float* __restrict__ Wv) {
    int mat = blockIdx.z;
    const float* W;
    int C, off;
    if (mat == 0)      { W = Wq; C = HIDDEN;  off = 0; }
    else if (mat == 1) { W = Wk; C = KV_COLS; off = HIDDEN; }
    else               { W = Wv; C = KV_COLS; off = HIDDEN + KV_COLS; }

    int col = blockIdx.x * 256 + threadIdx.x;
    if (col >= C) return;
    const float* p = W + (size_t)blockIdx.y * CHUNK_ROWS * C + col;
    float s = 0.f;
#pragma unroll 8
    for (int r = 0; r < CHUNK_ROWS; r++) s += p[(size_t)r * C];
    d_partial[blockIdx.y * TOT_COLS + off + col] = s;
}

// ---------------- stage 2: reduce partials (deterministic) ----------------
__global__ void __launch_bounds__(256) colsum_stage2() {
    int col = blockIdx.x * 256 + threadIdx.x;   // 0..6143
    float s = 0.f;
#pragma unroll
    for (int c = 0; c < NCHUNK; c++) s += d_partial[c * TOT_COLS + col];
    if (col < HIDDEN)                 d_cq[col] = s;
    else if (col < HIDDEN + KV_COLS)  d_ck[col - HIDDEN] = s;
    else                              d_cv[col - HIDDEN - KV_COLS] = s;
}

// ---------------- M[h,j] = sum_d cv[kvh*128+d] * Wo[(h*128+d)*HIDDEN + j] ----------------
__global__ void __launch_bounds__(256) compute_M(const float* __restrict__ Wo) {
    int j = blockIdx.x * 256 + threadIdx.x;     // 0..4095
    int h = blockIdx.y;                         // 0..31
    int kvh = h >> 2;
    const float* wp = Wo + (size_t)(h * HEAD_DIM) * HIDDEN + j;
    const float* cv = d_cv + kvh * HEAD_DIM;
    float s = 0.f;
#pragma unroll 8
    for (int d = 0; d < HEAD_DIM; d++) s += cv[d] * wp[(size_t)d * HIDDEN];
    d_M[h * HIDDEN + j] = s;
}

// ---------------- g table: g[h][delta] = sum_i A_i cos(delta*w_i) + B_i sin(delta*w_i) ----
__global__ void __launch_bounds__(256) compute_g() {
    __shared__ float sA[64], sB[64];
    int h = blockIdx.y;
    int kvh = h >> 2;
    if (threadIdx.x < 64) {
        int i = threadIdx.x;
        float q1 = d_cq[h * HEAD_DIM + i];
        float q2 = d_cq[h * HEAD_DIM + 64 + i];
        float k1 = d_ck[kvh * HEAD_DIM + i];
        float k2 = d_ck[kvh * HEAD_DIM + 64 + i];
        sA[i] = q1 * k1 + q2 * k2;
        sB[i] = q1 * k2 - q2 * k1;
    }
    __syncthreads();
    int delta = blockIdx.x * 256 + threadIdx.x;   // 0..2047
    double dd = (double)delta;
    const double LN10000 = 9.210340371976184;     // ln(10000)
    float acc = 0.f;
    for (int i = 0; i < 64; i++) {
        double omega = exp(-((double)(2 * i) / 128.0) * LN10000);
        double th = dd * omega;
        double sn, cs;
        sincos(th, &sn, &cs);
        acc += sA[i] * (float)cs + sB[i] * (float)sn;
    }
    d_g[h * SEQ + delta] = acc;
}

// ---------------- attention: online causal softmax over scores = a*ids[k]*g[q-k] ----------
__global__ void __launch_bounds__(256) attention(const int* __restrict__ ids) {
    __shared__ float s_g[SEQ];
    __shared__ float s_ids[SEQ];
    int h = blockIdx.y;
    int tid = threadIdx.x;
    for (int i = tid; i < SEQ; i += 256) {
        s_g[i] = d_g[h * SEQ + i];
        s_ids[i] = (float)ids[i];
    }
    __syncthreads();

    int warp = tid >> 5, lane = tid & 31;
    const float INV_SQRT_D = 0.08838834764831845f;  // 1/sqrt(128)

    for (int r = 0; r < 16; r++) {
        int q = blockIdx.x * 128 + r * 8 + warp;
        float alpha = s_ids[q] * INV_SQRT_D;
        float m = -CUDART_INF_F, l = 0.f, a = 0.f;
        for (int k = lane; k <= q; k += 32) {
            float s = alpha * s_ids[k] * s_g[q - k];
            if (s > m) {
                float sc = expf(m - s);   // m=-inf -> sc=0, safe
                l *= sc; a *= sc;
                m = s;
                l += 1.f; a += s_ids[k];
            } else if (s > m - 60.f) {
                float e = expf(s - m);
                l += e; a += e * s_ids[k];
            }
            // contributions below m-60 are < e^-60: exact zeros/denormals in the
            // reference's fp32 softmax too -> negligible.
        }
        // warp merge of (m, l, a)
#pragma unroll
        for (int off = 16; off; off >>= 1) {
            float m2 = __shfl_xor_sync(0xffffffffu, m, off);
            float l2 = __shfl_xor_sync(0xffffffffu, l, off);
            float a2 = __shfl_xor_sync(0xffffffffu, a, off);
            float mn = fmaxf(m, m2);
            float sc1 = (m == mn) ? 1.f : expf(m - mn);   // guards -inf - -inf = NaN
            float sc2 = (m2 == mn) ? 1.f : expf(m2 - mn);
            l = l * sc1 + l2 * sc2;
            a = a * sc1 + a2 * sc2;
            m = mn;
        }
        if (lane == 0) d_w[h * SEQ + q] = a / l;
    }
}

// ---------------- final: y[q, j] = sum_h w[h,q] * M[h,j] ----------------
__global__ void __launch_bounds__(256) final_proj(float* __restrict__ out) {
    __shared__ float s_w[32 * 64];
    int jb = blockIdx.x, qb = blockIdx.y;
    int tid = threadIdx.x;
    for (int i = tid; i < 32 * 64; i += 256) {
        int h = i >> 6, qq = i & 63;
        s_w[i] = d_w[h * SEQ + qb * 64 + qq];
    }
    __syncthreads();
    int j = jb * 256 + tid;
    float Mreg[32];
#pragma unroll
    for (int h = 0; h < 32; h++) Mreg[h] = d_M[h * HIDDEN + j];
    for (int qq = 0; qq < 64; qq++) {
        float acc = 0.f;
#pragma unroll
        for (int h = 0; h < 32; h++) acc += s_w[h * 64 + qq] * Mreg[h];
        out[(size_t)(qb * 64 + qq) * HIDDEN + j] = acc;
    }
}

// ---------------- launch ----------------
extern "C" void kernel_launch(void* const* d_in, const int* in_sizes, int n_in,
                              void* d_out, int out_size) {
    // Robustly map inputs by element count (order-preserving within equal sizes):
    // 2048: input_ids, position_ids ; 16777216: Wq, Wo ; 4194304: Wk, Wv
    const int* ids = nullptr;
    const float *Wq = nullptr, *Wk = nullptr, *Wv = nullptr, *Wo = nullptr;
    int seen2048 = 0, seen16m = 0, seen4m = 0;
    for (int i = 0; i < n_in; i++) {
        int sz = in_sizes[i];
        if (sz == SEQ) {
            if (seen2048++ == 0) ids = (const int*)d_in[i];           // input_ids first
        } else if (sz == HIDDEN * HIDDEN) {
            if (seen16m++ == 0) Wq = (const float*)d_in[i];
            else                Wo = (const float*)d_in[i];
        } else if (sz == HIDDEN * KV_COLS) {
            if (seen4m++ == 0)  Wk = (const float*)d_in[i];
            else                Wv = (const float*)d_in[i];
        }
    }
    float* out = (float*)d_out;

    colsum_stage1<<<dim3(16, NCHUNK, 3), 256>>>(Wq, Wk, Wv);
    colsum_stage2<<<TOT_COLS / 256, 256>>>();
    compute_M<<<dim3(HIDDEN / 256, NQH), 256>>>(Wo);
    compute_g<<<dim3(SEQ / 256, NQH), 256>>>();
    attention<<<dim3(SEQ / 128, NQH), 256>>>(ids);
    final_proj<<<dim3(HIDDEN / 256, SEQ / 64), 256>>>(out);
}

// round 2
// speedup vs baseline: 1.6032x; 1.6032x over previous
#include <cuda_runtime.h>
#include <math.h>
#include <math_constants.h>

// Problem constants
#define HEAD_DIM 128
#define NQH      32
#define NKVH     8
#define HIDDEN   4096
#define SEQ      2048
#define KV_COLS  1024          // NKVH * HEAD_DIM
#define NCHUNK   32
#define CHUNK_ROWS 128         // 4096 / NCHUNK
#define TOT_COLS 6144          // HIDDEN + 2*KV_COLS

// ---------------- scratch (no allocations allowed) ----------------
__device__ float  d_partial[NCHUNK * TOT_COLS];  // colsum partials
__device__ float  d_cq[HIDDEN];                  // colsum(Wq)
__device__ float  d_ck[KV_COLS];                 // colsum(Wk)
__device__ float  d_cv[KV_COLS];                 // colsum(Wv)
__device__ float2 d_trig[64 * SEQ];              // (cos,sin)(delta*omega_i), head-independent
__device__ float  d_g[NQH * SEQ];                // per-head relative-position score table
__device__ float  d_M[NQH * HIDDEN];             // M[h,j] = sum_d cv[kvh,d]*Wo[h*128+d, j]
__device__ float  d_w[NQH * SEQ];                // w[h,q] = sum_k attn(h,q,k)*ids[k]

// ---------------- stage 1: partial column sums of Wq, Wk, Wv ----------------
__global__ void __launch_bounds__(256) colsum_stage1(const float* __restrict__ Wq,
                                                     const float* __restrict__ Wk,
                                                     const float* __restrict__ Wv) {
    int mat = blockIdx.z;
    const float* W;
    int C, off;
    if (mat == 0)      { W = Wq; C = HIDDEN;  off = 0; }
    else if (mat == 1) { W = Wk; C = KV_COLS; off = HIDDEN; }
    else               { W = Wv; C = KV_COLS; off = HIDDEN + KV_COLS; }

    int col = blockIdx.x * 256 + threadIdx.x;
    if (col >= C) return;
    const float* p = W + (size_t)blockIdx.y * CHUNK_ROWS * C + col;
    float s = 0.f;
#pragma unroll 8
    for (int r = 0; r < CHUNK_ROWS; r++) s += p[(size_t)r * C];
    d_partial[blockIdx.y * TOT_COLS + off + col] = s;
}

// ---------------- stage 2: reduce partials (deterministic) ----------------
__global__ void __launch_bounds__(256) colsum_stage2() {
    int col = blockIdx.x * 256 + threadIdx.x;   // 0..6143
    float s = 0.f;
#pragma unroll
    for (int c = 0; c < NCHUNK; c++) s += d_partial[c * TOT_COLS + col];
    if (col < HIDDEN)                 d_cq[col] = s;
    else if (col < HIDDEN + KV_COLS)  d_ck[col - HIDDEN] = s;
    else                              d_cv[col - HIDDEN - KV_COLS] = s;
}

// ---------------- M[h,j] = sum_d cv[kvh*128+d] * Wo[(h*128+d)*HIDDEN + j] ----------------
__global__ void __launch_bounds__(256) compute_M(const float* __restrict__ Wo) {
    int j = blockIdx.x * 256 + threadIdx.x;     // 0..4095
    int h = blockIdx.y;                         // 0..31
    int kvh = h >> 2;
    const float* wp = Wo + (size_t)(h * HEAD_DIM) * HIDDEN + j;
    const float* cv = d_cv + kvh * HEAD_DIM;
    float s = 0.f;
#pragma unroll 8
    for (int d = 0; d < HEAD_DIM; d++) s += cv[d] * wp[(size_t)d * HIDDEN];
    d_M[h * HIDDEN + j] = s;
}

// ---------------- trig table: (cos,sin)(delta * omega_i), computed ONCE (head-indep) ------
__global__ void __launch_bounds__(256) compute_trig() {
    int idx = blockIdx.x * 256 + threadIdx.x;   // 0 .. 64*2048-1
    int i = idx >> 11;                          // frequency index 0..63
    int delta = idx & (SEQ - 1);                // 0..2047
    const double LN10000 = 9.210340371976184;   // ln(10000)
    double omega = exp(-((double)(2 * i) / 128.0) * LN10000);
    double th = (double)delta * omega;
    double sn, cs;
    sincos(th, &sn, &cs);
    d_trig[idx] = make_float2((float)cs, (float)sn);
}

// ---------------- g table: g[h][delta] = sum_i A_i*cos + B_i*sin ----------------
__global__ void __launch_bounds__(256) compute_g() {
    __shared__ float sA[64], sB[64];
    int h = blockIdx.y;
    int kvh = h >> 2;
    if (threadIdx.x < 64) {
        int i = threadIdx.x;
        float q1 = d_cq[h * HEAD_DIM + i];
        float q2 = d_cq[h * HEAD_DIM + 64 + i];
        float k1 = d_ck[kvh * HEAD_DIM + i];
        float k2 = d_ck[kvh * HEAD_DIM + 64 + i];
        sA[i] = q1 * k1 + q2 * k2;
        sB[i] = q1 * k2 - q2 * k1;
    }
    __syncthreads();
    int delta = blockIdx.x * 256 + threadIdx.x;   // 0..2047
    float acc = 0.f;
#pragma unroll 8
    for (int i = 0; i < 64; i++) {
        float2 t = d_trig[i * SEQ + delta];       // coalesced, L2-resident (1 MB table)
        acc += sA[i] * t.x + sB[i] * t.y;
    }
    d_g[h * SEQ + delta] = acc;
}

// ---------------- attention: two-pass causal softmax, scores = alpha*ids[k]*g[q-k] --------
__global__ void __launch_bounds__(256) attention(const int* __restrict__ ids) {
    __shared__ float s_g[SEQ];
    __shared__ float s_ids[SEQ];
    int h = blockIdx.y;
    int tid = threadIdx.x;
    for (int i = tid; i < SEQ; i += 256) {
        s_g[i] = d_g[h * SEQ + i];
        s_ids[i] = (float)ids[i];
    }
    __syncthreads();

    int warp = tid >> 5, lane = tid & 31;
    int slot = blockIdx.x * 8 + warp;             // 0..127
    const float INV_SQRT_D = 0.08838834764831845f;  // 1/sqrt(128)

    for (int r = 0; r < 16; r++) {
        int q = slot + 128 * r;                   // strided: balances triangular work
        float alpha = s_ids[q] * INV_SQRT_D;      // >= 0 always (ids in [0,100))
        const float* gq = s_g + q;                // g[q-k] = gq[-k]

        // ---- pass 1: branchless max of u = ids[k]*g[q-k], k<=q, 4 independent chains
        float m0 = -CUDART_INF_F, m1 = m0, m2 = m0, m3 = m0;
        int k = lane;
        for (; k + 96 <= q; k += 128) {
            m0 = fmaxf(m0, s_ids[k]      * gq[-k]);
            m1 = fmaxf(m1, s_ids[k + 32] * gq[-(k + 32)]);
            m2 = fmaxf(m2, s_ids[k + 64] * gq[-(k + 64)]);
            m3 = fmaxf(m3, s_ids[k + 96] * gq[-(k + 96)]);
        }
        for (; k <= q; k += 32) m0 = fmaxf(m0, s_ids[k] * gq[-k]);
        float umax = fmaxf(fmaxf(m0, m1), fmaxf(m2, m3));
#pragma unroll
        for (int off = 16; off; off >>= 1)
            umax = fmaxf(umax, __shfl_xor_sync(0xffffffffu, umax, off));

        float smax = alpha * umax;
        // only u with alpha*u > smax-60 contribute (< e^-60 otherwise, below ref's
        // fp32 underflow floor). alpha==0 (ids[q]==0) => all scores 0 => uniform.
        float thr = (alpha > 0.f) ? (umax - 60.f / alpha) : -CUDART_INF_F;

        // ---- pass 2: predicated accumulate; __expf fires on ~1% of elements
        float l = 0.f, a = 0.f;
        for (k = lane; k <= q; k += 32) {
            float idk = s_ids[k];
            float u = idk * gq[-k];
            if (u > thr) {
                float e = __expf(alpha * u - smax);
                l += e; a += e * idk;
            }
        }
#pragma unroll
        for (int off = 16; off; off >>= 1) {
            l += __shfl_xor_sync(0xffffffffu, l, off);
            a += __shfl_xor_sync(0xffffffffu, a, off);
        }
        if (lane == 0) d_w[h * SEQ + q] = a / l;
    }
}

// ---------------- final: y[q, j] = sum_h w[h,q] * M[h,j] ----------------
__global__ void __launch_bounds__(256) final_proj(float* __restrict__ out) {
    __shared__ float s_w[32 * 64];
    int jb = blockIdx.x, qb = blockIdx.y;
    int tid = threadIdx.x;
    for (int i = tid; i < 32 * 64; i += 256) {
        int h = i >> 6, qq = i & 63;
        s_w[i] = d_w[h * SEQ + qb * 64 + qq];
    }
    __syncthreads();
    int j = jb * 256 + tid;
    float Mreg[32];
#pragma unroll
    for (int h = 0; h < 32; h++) Mreg[h] = d_M[h * HIDDEN + j];
    for (int qq = 0; qq < 64; qq++) {
        float acc = 0.f;
#pragma unroll
        for (int h = 0; h < 32; h++) acc += s_w[h * 64 + qq] * Mreg[h];
        out[(size_t)(qb * 64 + qq) * HIDDEN + j] = acc;
    }
}

// ---------------- launch ----------------
extern "C" void kernel_launch(void* const* d_in, const int* in_sizes, int n_in,
                              void* d_out, int out_size) {
    // Map inputs by element count (order-preserving within equal sizes):
    // 2048: input_ids, position_ids ; 16777216: Wq, Wo ; 4194304: Wk, Wv
    const int* ids = nullptr;
    const float *Wq = nullptr, *Wk = nullptr, *Wv = nullptr, *Wo = nullptr;
    int seen2048 = 0, seen16m = 0, seen4m = 0;
    for (int i = 0; i < n_in; i++) {
        int sz = in_sizes[i];
        if (sz == SEQ) {
            if (seen2048++ == 0) ids = (const int*)d_in[i];           // input_ids first
        } else if (sz == HIDDEN * HIDDEN) {
            if (seen16m++ == 0) Wq = (const float*)d_in[i];
            else                Wo = (const float*)d_in[i];
        } else if (sz == HIDDEN * KV_COLS) {
            if (seen4m++ == 0)  Wk = (const float*)d_in[i];
            else                Wv = (const float*)d_in[i];
        }
    }
    float* out = (float*)d_out;

    colsum_stage1<<<dim3(16, NCHUNK, 3), 256>>>(Wq, Wk, Wv);
    colsum_stage2<<<TOT_COLS / 256, 256>>>();
    compute_M<<<dim3(HIDDEN / 256, NQH), 256>>>(Wo);
    compute_trig<<<(64 * SEQ) / 256, 256>>>();
    compute_g<<<dim3(SEQ / 256, NQH), 256>>>();
    attention<<<dim3(SEQ / 128, NQH), 256>>>(ids);
    final_proj<<<dim3(HIDDEN / 256, SEQ / 64), 256>>>(out);
}